// round 1
// baseline (speedup 1.0000x reference)
#include <cuda_runtime.h>
#include <cuda_bf16.h>

// ---------------------------------------------------------------------------
// DiagonalSSMLayer: y = C*h + D*x, h_t = sigmoid(Wa x + ba) * h_{t-1} + B x
// Shapes: x[8,4096,1024], state=256. All fp32.
// Inputs (metadata order): x, Wa_w[256,1024], Wa_b[256], B_w[256,1024],
//                          C_w[1024,256], D_w[1024,1024]
// ---------------------------------------------------------------------------

#define BATCH   8
#define SEQ     4096
#define DMODEL  1024
#define STATE   256
#define MTOT    (BATCH * SEQ)        // 32768
#define NCHUNK  32
#define CHUNK   (SEQ / NCHUNK)       // 128

// Scratch (allocation-free rule: __device__ globals)
__device__ float g_A[MTOT * STATE];      // sigmoid gate a
__device__ float g_B[MTOT * STATE];      // b = B x
__device__ float g_H[MTOT * STATE];      // scan result h
__device__ float g_aggA[BATCH * NCHUNK * STATE];
__device__ float g_aggB[BATCH * NCHUNK * STATE];
__device__ float g_carry[BATCH * NCHUNK * STATE];

// ------------------------- register-blocked SGEMM (NT) ---------------------
// C[m][n] = sum_k A[m][k] * W[n][k];  A row-major [M,K], W row-major [N,K]
#define BM 128
#define BN 128
#define BK 16
#define TM 8
#define TN 8
#define PAD 4

__device__ __forceinline__ void gemm_mainloop(
    const float* __restrict__ Ag,   // A + blockRow*BM*K
    const float* __restrict__ Wg,   // W + blockCol*BN*K
    int K,
    float (&As)[BK][BM + PAD], float (&Bs)[BK][BN + PAD],
    float (&acc)[TM][TN])
{
    const int tid = threadIdx.x;
    const int lr = tid >> 2;           // 0..63
    const int lc = (tid & 3) << 2;     // 0,4,8,12
    const int tx = tid & 15;
    const int ty = tid >> 4;

    for (int k0 = 0; k0 < K; k0 += BK) {
        float4 a0 = *reinterpret_cast<const float4*>(Ag + (size_t)lr * K + k0 + lc);
        float4 a1 = *reinterpret_cast<const float4*>(Ag + (size_t)(lr + 64) * K + k0 + lc);
        float4 b0 = *reinterpret_cast<const float4*>(Wg + (size_t)lr * K + k0 + lc);
        float4 b1 = *reinterpret_cast<const float4*>(Wg + (size_t)(lr + 64) * K + k0 + lc);

        As[lc + 0][lr] = a0.x; As[lc + 1][lr] = a0.y;
        As[lc + 2][lr] = a0.z; As[lc + 3][lr] = a0.w;
        As[lc + 0][lr + 64] = a1.x; As[lc + 1][lr + 64] = a1.y;
        As[lc + 2][lr + 64] = a1.z; As[lc + 3][lr + 64] = a1.w;

        Bs[lc + 0][lr] = b0.x; Bs[lc + 1][lr] = b0.y;
        Bs[lc + 2][lr] = b0.z; Bs[lc + 3][lr] = b0.w;
        Bs[lc + 0][lr + 64] = b1.x; Bs[lc + 1][lr + 64] = b1.y;
        Bs[lc + 2][lr + 64] = b1.z; Bs[lc + 3][lr + 64] = b1.w;

        __syncthreads();

        #pragma unroll
        for (int kk = 0; kk < BK; kk++) {
            float ar[TM], br[TN];
            #pragma unroll
            for (int i = 0; i < TM; i++) ar[i] = As[kk][ty * TM + i];
            #pragma unroll
            for (int j = 0; j < TN; j++) br[j] = Bs[kk][tx * TN + j];
            #pragma unroll
            for (int i = 0; i < TM; i++)
                #pragma unroll
                for (int j = 0; j < TN; j++)
                    acc[i][j] += ar[i] * br[j];
        }
        __syncthreads();
    }
}

// Kernel 1: a = sigmoid(x Wa^T + ba), b = x B^T
__global__ void __launch_bounds__(256, 2) k_gemm_ab(
    const float* __restrict__ x, const float* __restrict__ Wa,
    const float* __restrict__ ba, const float* __restrict__ Bw)
{
    __shared__ float As[BK][BM + PAD];
    __shared__ float Bs[BK][BN + PAD];
    float acc[TM][TN] = {};

    const int bm = blockIdx.y;        // 0..255
    const int bn = blockIdx.x;        // 0..3: 0,1->Wa; 2,3->Bw
    const bool isA = bn < 2;
    const float* W = isA ? (Wa + (size_t)bn * BN * DMODEL)
                         : (Bw + (size_t)(bn - 2) * BN * DMODEL);

    gemm_mainloop(x + (size_t)bm * BM * DMODEL, W, DMODEL, As, Bs, acc);

    const int tx = threadIdx.x & 15;
    const int ty = threadIdx.x >> 4;
    const int m0 = bm * BM + ty * TM;
    const int n0 = (bn & 1) * BN + tx * TN;

    #pragma unroll
    for (int i = 0; i < TM; i++) {
        #pragma unroll
        for (int j = 0; j < TN; j++) {
            const int m = m0 + i, n = n0 + j;
            float v = acc[i][j];
            if (isA) {
                v = 1.0f / (1.0f + __expf(-(v + ba[n])));
                g_A[(size_t)m * STATE + n] = v;
            } else {
                g_B[(size_t)m * STATE + n] = v;
            }
        }
    }
}

// Kernel 2: per-chunk aggregates (prod a, local end-state)
__global__ void __launch_bounds__(256) k_scan_agg()
{
    const int chunk = blockIdx.x;     // 0..31
    const int b = blockIdx.y;         // 0..7
    const int n = threadIdx.x;        // 0..255
    const size_t base = ((size_t)(b * SEQ + chunk * CHUNK)) * STATE + n;

    float Aacc = 1.0f, Bacc = 0.0f;
    #pragma unroll 4
    for (int s = 0; s < CHUNK; s++) {
        float a = g_A[base + (size_t)s * STATE];
        float bb = g_B[base + (size_t)s * STATE];
        Bacc = a * Bacc + bb;
        Aacc *= a;
    }
    const size_t idx = ((size_t)(b * NCHUNK + chunk)) * STATE + n;
    g_aggA[idx] = Aacc;
    g_aggB[idx] = Bacc;
}

// Kernel 3: exclusive scan of aggregates -> carry (h value entering each chunk)
__global__ void __launch_bounds__(256) k_scan_carry()
{
    const int b = blockIdx.x;
    const int n = threadIdx.x;
    float h = 0.0f;                    // h_{-1} = 0
    for (int c = 0; c < NCHUNK; c++) {
        const size_t idx = ((size_t)(b * NCHUNK + c)) * STATE + n;
        g_carry[idx] = h;
        h = g_aggA[idx] * h + g_aggB[idx];
    }
}

// Kernel 4: replay local recurrence with carry, write h
__global__ void __launch_bounds__(256) k_scan_apply()
{
    const int chunk = blockIdx.x;
    const int b = blockIdx.y;
    const int n = threadIdx.x;
    const size_t base = ((size_t)(b * SEQ + chunk * CHUNK)) * STATE + n;

    float h = g_carry[((size_t)(b * NCHUNK + chunk)) * STATE + n];
    #pragma unroll 4
    for (int s = 0; s < CHUNK; s++) {
        const size_t idx = base + (size_t)s * STATE;
        h = g_A[idx] * h + g_B[idx];
        g_H[idx] = h;
    }
}

// Kernel 5: y = h C^T + x D^T
__global__ void __launch_bounds__(256, 2) k_gemm_y(
    const float* __restrict__ x, const float* __restrict__ Cw,
    const float* __restrict__ Dw, float* __restrict__ out)
{
    __shared__ float As[BK][BM + PAD];
    __shared__ float Bs[BK][BN + PAD];
    float acc[TM][TN] = {};

    const int bm = blockIdx.y;        // 0..255
    const int bn = blockIdx.x;        // 0..7

    gemm_mainloop(g_H + (size_t)bm * BM * STATE,
                  Cw + (size_t)bn * BN * STATE, STATE, As, Bs, acc);
    gemm_mainloop(x + (size_t)bm * BM * DMODEL,
                  Dw + (size_t)bn * BN * DMODEL, DMODEL, As, Bs, acc);

    const int tx = threadIdx.x & 15;
    const int ty = threadIdx.x >> 4;
    const int m0 = bm * BM + ty * TM;
    const int n0 = bn * BN + tx * TN;

    #pragma unroll
    for (int i = 0; i < TM; i++) {
        #pragma unroll
        for (int j = 0; j < TN; j++) {
            out[(size_t)(m0 + i) * DMODEL + (n0 + j)] = acc[i][j];
        }
    }
}

extern "C" void kernel_launch(void* const* d_in, const int* in_sizes, int n_in,
                              void* d_out, int out_size)
{
    const float* x   = (const float*)d_in[0];
    const float* Wa  = (const float*)d_in[1];
    const float* Wab = (const float*)d_in[2];
    const float* Bw  = (const float*)d_in[3];
    const float* Cw  = (const float*)d_in[4];
    const float* Dw  = (const float*)d_in[5];
    float* out = (float*)d_out;

    dim3 gAB(4, MTOT / BM);                    // N=512
    k_gemm_ab<<<gAB, 256>>>(x, Wa, Wab, Bw);

    k_scan_agg<<<dim3(NCHUNK, BATCH), 256>>>();
    k_scan_carry<<<BATCH, 256>>>();
    k_scan_apply<<<dim3(NCHUNK, BATCH), 256>>>();

    dim3 gY(DMODEL / BN, MTOT / BM);           // N=1024
    k_gemm_y<<<gY, 256>>>(x, Cw, Dw, out);
}

// round 4
// speedup vs baseline: 2.3135x; 2.3135x over previous
#include <cuda_runtime.h>
#include <cuda_bf16.h>
#include <cstdint>

// ---------------------------------------------------------------------------
// DiagonalSSMLayer via mma.sync bf16 (split hi/lo, 3-product) + chunked scan.
// tcgen05 is unavailable (ptxas target is compute_100, not 100a).
// y = C*h + D*x,  h_t = sigmoid(Wa x + ba) * h_{t-1} + B x
// ---------------------------------------------------------------------------

#define BATCH   8
#define SEQ     4096
#define DMODEL  1024
#define STATE   256
#define MTOT    (BATCH * SEQ)        // 32768
#define NCHUNK  64
#define CHUNK   (SEQ / NCHUNK)       // 64

typedef __nv_bfloat16 bf16;

// ---- scratch ----
__device__ __align__(16) float g_A[(size_t)MTOT * STATE];
__device__ __align__(16) float g_B[(size_t)MTOT * STATE];
__device__ __align__(16) float g_aggA[BATCH * NCHUNK * STATE];
__device__ __align__(16) float g_aggB[BATCH * NCHUNK * STATE];
__device__ __align__(16) float g_carry[BATCH * NCHUNK * STATE];

__device__ __align__(16) bf16 g_xhi[(size_t)MTOT * DMODEL];
__device__ __align__(16) bf16 g_xlo[(size_t)MTOT * DMODEL];
__device__ __align__(16) bf16 g_hhi[(size_t)MTOT * STATE];
__device__ __align__(16) bf16 g_hlo[(size_t)MTOT * STATE];
__device__ __align__(16) bf16 g_Wabhi[2 * STATE * DMODEL];
__device__ __align__(16) bf16 g_Wablo[2 * STATE * DMODEL];
__device__ __align__(16) bf16 g_Chi[DMODEL * STATE];
__device__ __align__(16) bf16 g_Clo[DMODEL * STATE];
__device__ __align__(16) bf16 g_Dhi[(size_t)DMODEL * DMODEL];
__device__ __align__(16) bf16 g_Dlo[(size_t)DMODEL * DMODEL];

// ---------------------------------------------------------------------------
// SMEM tile geometry: per stage 4 tiles (Ahi, Alo, Bhi, Blo), each 128 rows of
// 32 bf16 (64B) padded to 80B stride (conflict-free ldmatrix).
// ---------------------------------------------------------------------------
#define ROWB     80
#define TILE_B   (128 * ROWB)        // 10240
#define STAGE_B  (4 * TILE_B)        // 40960
#define SMEM_SZ  (2 * STAGE_B)       // 81920

__device__ __forceinline__ uint32_t smem_u32(const void* p) {
    uint32_t a;
    asm("{ .reg .u64 t; cvta.to.shared.u64 t, %1; cvt.u32.u64 %0, t; }" : "=r"(a) : "l"(p));
    return a;
}

#define CP_ASYNC(s, g) \
    asm volatile("cp.async.cg.shared.global [%0], [%1], 16;" :: "r"(s), "l"(g))
#define CP_COMMIT() asm volatile("cp.async.commit_group;" ::: "memory")
#define CP_WAIT1()  asm volatile("cp.async.wait_group 1;" ::: "memory")

#define LDMX4(r0, r1, r2, r3, addr) \
    asm volatile("ldmatrix.sync.aligned.m8n8.x4.shared.b16 {%0,%1,%2,%3}, [%4];" \
                 : "=r"(r0), "=r"(r1), "=r"(r2), "=r"(r3) : "r"(addr))

#define MMA_BF16(d, a, b0, b1) \
    asm volatile("mma.sync.aligned.m16n8k16.row.col.f32.bf16.bf16.f32 " \
                 "{%0,%1,%2,%3}, {%4,%5,%6,%7}, {%8,%9}, {%0,%1,%2,%3};" \
                 : "+f"((d)[0]), "+f"((d)[1]), "+f"((d)[2]), "+f"((d)[3]) \
                 : "r"((a)[0]), "r"((a)[1]), "r"((a)[2]), "r"((a)[3]), \
                   "r"(b0), "r"(b1))

// Load one stage: 4 tiles of 128x32 bf16 into smem (cp.async, 16B ops)
__device__ __forceinline__ void stage_load(
    const bf16* __restrict__ Ahi, const bf16* __restrict__ Alo, int ldA,
    const bf16* __restrict__ Bhi, const bf16* __restrict__ Blo, int ldB,
    int k0, uint32_t st)
{
    const int tid = threadIdx.x;
    const bf16* srcs[4] = {Ahi, Alo, Bhi, Blo};
    #pragma unroll
    for (int t = 0; t < 4; t++) {
        const int ld = (t < 2) ? ldA : ldB;
        #pragma unroll
        for (int i = 0; i < 2; i++) {
            const int idx = i * 256 + tid;
            const int row = idx >> 2, c = idx & 3;
            const bf16* g = srcs[t] + (size_t)row * ld + k0 + c * 8;
            CP_ASYNC(st + t * TILE_B + row * ROWB + c * 16, g);
        }
    }
}

// Compute one stage: 3-product split-bf16 accumulation, warp tile 32x64
__device__ __forceinline__ void compute_stage(uint32_t st, int wm, int wn,
                                              float (&acc)[2][8][4])
{
    const int lane = threadIdx.x & 31;
    const uint32_t a_row  = wm * 32 + (lane & 15);
    const uint32_t a_coff = (lane >> 4) * 16;
    const uint32_t b_rowc = wn * 64 + (lane & 7) + ((lane >> 4) & 1) * 8;
    const uint32_t b_coff = ((lane >> 3) & 1) * 16;

    #pragma unroll
    for (int ks = 0; ks < 2; ks++) {
        const uint32_t kb = ks * 32;
        uint32_t ahi[2][4], alo[2][4];
        #pragma unroll
        for (int t = 0; t < 2; t++) {
            uint32_t ad = st + (a_row + t * 16) * ROWB + kb + a_coff;
            LDMX4(ahi[t][0], ahi[t][1], ahi[t][2], ahi[t][3], ad);
            LDMX4(alo[t][0], alo[t][1], alo[t][2], alo[t][3], ad + TILE_B);
        }
        #pragma unroll
        for (int j = 0; j < 4; j++) {         // ntile pairs (2j, 2j+1)
            uint32_t bd = st + 2 * TILE_B + (b_rowc + j * 16) * ROWB + kb + b_coff;
            uint32_t bh[4], bl[4];
            LDMX4(bh[0], bh[1], bh[2], bh[3], bd);
            LDMX4(bl[0], bl[1], bl[2], bl[3], bd + TILE_B);
            #pragma unroll
            for (int s = 0; s < 2; s++) {
                #pragma unroll
                for (int t = 0; t < 2; t++) {
                    MMA_BF16(acc[t][2 * j + s], ahi[t], bh[2 * s], bh[2 * s + 1]);
                    MMA_BF16(acc[t][2 * j + s], ahi[t], bl[2 * s], bl[2 * s + 1]);
                    MMA_BF16(acc[t][2 * j + s], alo[t], bh[2 * s], bh[2 * s + 1]);
                }
            }
        }
    }
}

// Full mainloop over nchunks K-chunks of 32 (double-buffered)
__device__ __forceinline__ void gemm_main(
    const bf16* __restrict__ Ahi, const bf16* __restrict__ Alo, int ldA,
    const bf16* __restrict__ Bhi, const bf16* __restrict__ Blo, int ldB,
    int nchunks, uint32_t sbase, int wm, int wn, float (&acc)[2][8][4])
{
    stage_load(Ahi, Alo, ldA, Bhi, Blo, ldB, 0, sbase);
    CP_COMMIT();
    for (int c = 0; c < nchunks; c++) {
        if (c + 1 < nchunks)
            stage_load(Ahi, Alo, ldA, Bhi, Blo, ldB, (c + 1) * 32,
                       sbase + ((c + 1) & 1) * STAGE_B);
        CP_COMMIT();
        CP_WAIT1();
        __syncthreads();
        compute_stage(sbase + (c & 1) * STAGE_B, wm, wn, acc);
        __syncthreads();
    }
}

__device__ __forceinline__ float sigf(float t) {
    return 1.0f / (1.0f + __expf(-t));
}

// ---------------------------------------------------------------------------
// GEMM1: [a|b] = x * [Wa;Bw]^T  (M=32768, N=512, K=1024)
// ---------------------------------------------------------------------------
__global__ void __launch_bounds__(256) k_gemm1(const float* __restrict__ ba)
{
    extern __shared__ char smem[];
    const uint32_t sbase = smem_u32(smem);
    const int wid = threadIdx.x >> 5, lane = threadIdx.x & 31;
    const int wm = wid & 3, wn = wid >> 2;

    const size_t m0 = (size_t)blockIdx.y * 128;
    const size_t n0 = (size_t)blockIdx.x * 128;
    float acc[2][8][4] = {};

    gemm_main(g_xhi + m0 * DMODEL, g_xlo + m0 * DMODEL, DMODEL,
              g_Wabhi + n0 * DMODEL, g_Wablo + n0 * DMODEL, DMODEL,
              32, sbase, wm, wn, acc);

    const bool isA = (n0 < 256);
    #pragma unroll
    for (int t = 0; t < 2; t++) {
        #pragma unroll
        for (int j = 0; j < 8; j++) {
            const int row = (int)m0 + wm * 32 + t * 16 + (lane >> 2);
            const int col = (int)n0 + wn * 64 + j * 8 + (lane & 3) * 2;
            if (isA) {
                const float b0 = __ldg(ba + col), b1 = __ldg(ba + col + 1);
                float2 v0 = { sigf(acc[t][j][0] + b0), sigf(acc[t][j][1] + b1) };
                float2 v1 = { sigf(acc[t][j][2] + b0), sigf(acc[t][j][3] + b1) };
                *reinterpret_cast<float2*>(g_A + (size_t)row * STATE + col) = v0;
                *reinterpret_cast<float2*>(g_A + (size_t)(row + 8) * STATE + col) = v1;
            } else {
                const int cb = col - 256;
                float2 v0 = { acc[t][j][0], acc[t][j][1] };
                float2 v1 = { acc[t][j][2], acc[t][j][3] };
                *reinterpret_cast<float2*>(g_B + (size_t)row * STATE + cb) = v0;
                *reinterpret_cast<float2*>(g_B + (size_t)(row + 8) * STATE + cb) = v1;
            }
        }
    }
}

// ---------------------------------------------------------------------------
// GEMM2: y = h*C^T + x*D^T  (M=32768, N=1024; K=256 then K=1024)
// ---------------------------------------------------------------------------
__global__ void __launch_bounds__(256) k_gemm2(float* __restrict__ out)
{
    extern __shared__ char smem[];
    const uint32_t sbase = smem_u32(smem);
    const int wid = threadIdx.x >> 5, lane = threadIdx.x & 31;
    const int wm = wid & 3, wn = wid >> 2;

    const size_t m0 = (size_t)blockIdx.y * 128;
    const size_t n0 = (size_t)blockIdx.x * 128;
    float acc[2][8][4] = {};

    gemm_main(g_hhi + m0 * STATE, g_hlo + m0 * STATE, STATE,
              g_Chi + n0 * STATE, g_Clo + n0 * STATE, STATE,
              8, sbase, wm, wn, acc);
    gemm_main(g_xhi + m0 * DMODEL, g_xlo + m0 * DMODEL, DMODEL,
              g_Dhi + n0 * DMODEL, g_Dlo + n0 * DMODEL, DMODEL,
              32, sbase, wm, wn, acc);

    #pragma unroll
    for (int t = 0; t < 2; t++) {
        #pragma unroll
        for (int j = 0; j < 8; j++) {
            const int row = (int)m0 + wm * 32 + t * 16 + (lane >> 2);
            const int col = (int)n0 + wn * 64 + j * 8 + (lane & 3) * 2;
            float2 v0 = { acc[t][j][0], acc[t][j][1] };
            float2 v1 = { acc[t][j][2], acc[t][j][3] };
            *reinterpret_cast<float2*>(out + (size_t)row * DMODEL + col) = v0;
            *reinterpret_cast<float2*>(out + (size_t)(row + 8) * DMODEL + col) = v1;
        }
    }
}

// ---------------------------------------------------------------------------
// fp32 -> (hi, lo) bf16 split
// ---------------------------------------------------------------------------
__global__ void __launch_bounds__(256) k_cvt(const float* __restrict__ in,
                                             bf16* __restrict__ hi,
                                             bf16* __restrict__ lo, int n)
{
    int i = (blockIdx.x * 256 + threadIdx.x) * 4;
    if (i >= n) return;
    float4 v = *reinterpret_cast<const float4*>(in + i);
    bf16 h0 = __float2bfloat16(v.x), h1 = __float2bfloat16(v.y);
    bf16 h2 = __float2bfloat16(v.z), h3 = __float2bfloat16(v.w);
    ushort4 hs, ls;
    hs.x = __bfloat16_as_ushort(h0); hs.y = __bfloat16_as_ushort(h1);
    hs.z = __bfloat16_as_ushort(h2); hs.w = __bfloat16_as_ushort(h3);
    ls.x = __bfloat16_as_ushort(__float2bfloat16(v.x - __bfloat162float(h0)));
    ls.y = __bfloat16_as_ushort(__float2bfloat16(v.y - __bfloat162float(h1)));
    ls.z = __bfloat16_as_ushort(__float2bfloat16(v.z - __bfloat162float(h2)));
    ls.w = __bfloat16_as_ushort(__float2bfloat16(v.w - __bfloat162float(h3)));
    *reinterpret_cast<ushort4*>(reinterpret_cast<unsigned short*>(hi) + i) = hs;
    *reinterpret_cast<ushort4*>(reinterpret_cast<unsigned short*>(lo) + i) = ls;
}

// ---------------------------------------------------------------------------
// Scan kernels
// ---------------------------------------------------------------------------
__global__ void __launch_bounds__(256) k_scan_agg()
{
    const int chunk = blockIdx.x, b = blockIdx.y, n = threadIdx.x;
    const size_t base = ((size_t)(b * SEQ + chunk * CHUNK)) * STATE + n;
    float Aacc = 1.0f, Bacc = 0.0f;
    #pragma unroll 8
    for (int s = 0; s < CHUNK; s++) {
        float a  = g_A[base + (size_t)s * STATE];
        float bb = g_B[base + (size_t)s * STATE];
        Bacc = a * Bacc + bb;
        Aacc *= a;
    }
    const size_t idx = ((size_t)(b * NCHUNK + chunk)) * STATE + n;
    g_aggA[idx] = Aacc;
    g_aggB[idx] = Bacc;
}

__global__ void __launch_bounds__(256) k_scan_carry()
{
    const int b = blockIdx.x, n = threadIdx.x;
    float h = 0.0f;
    for (int c = 0; c < NCHUNK; c++) {
        const size_t idx = ((size_t)(b * NCHUNK + c)) * STATE + n;
        g_carry[idx] = h;
        h = g_aggA[idx] * h + g_aggB[idx];
    }
}

__global__ void __launch_bounds__(256) k_scan_apply()
{
    const int chunk = blockIdx.x, b = blockIdx.y, n = threadIdx.x;
    const size_t base = ((size_t)(b * SEQ + chunk * CHUNK)) * STATE + n;
    float h = g_carry[((size_t)(b * NCHUNK + chunk)) * STATE + n];
    #pragma unroll 8
    for (int s = 0; s < CHUNK; s++) {
        const size_t idx = base + (size_t)s * STATE;
        h = g_A[idx] * h + g_B[idx];
        bf16 hh = __float2bfloat16(h);
        g_hhi[idx] = hh;
        g_hlo[idx] = __float2bfloat16(h - __bfloat162float(hh));
    }
}

// ---------------------------------------------------------------------------
// Launch
// ---------------------------------------------------------------------------
extern "C" void kernel_launch(void* const* d_in, const int* in_sizes, int n_in,
                              void* d_out, int out_size)
{
    const float* x   = (const float*)d_in[0];
    const float* Wa  = (const float*)d_in[1];
    const float* Wab = (const float*)d_in[2];
    const float* Bw  = (const float*)d_in[3];
    const float* Cw  = (const float*)d_in[4];
    const float* Dw  = (const float*)d_in[5];
    float* out = (float*)d_out;

    void *xhi, *xlo, *wabhi, *wablo, *chi, *clo, *dhi, *dlo;
    cudaGetSymbolAddress(&xhi,   g_xhi);
    cudaGetSymbolAddress(&xlo,   g_xlo);
    cudaGetSymbolAddress(&wabhi, g_Wabhi);
    cudaGetSymbolAddress(&wablo, g_Wablo);
    cudaGetSymbolAddress(&chi,   g_Chi);
    cudaGetSymbolAddress(&clo,   g_Clo);
    cudaGetSymbolAddress(&dhi,   g_Dhi);
    cudaGetSymbolAddress(&dlo,   g_Dlo);

    cudaFuncSetAttribute(k_gemm1, cudaFuncAttributeMaxDynamicSharedMemorySize, SMEM_SZ);
    cudaFuncSetAttribute(k_gemm2, cudaFuncAttributeMaxDynamicSharedMemorySize, SMEM_SZ);

    {   // conversions
        int n = MTOT * DMODEL;
        k_cvt<<<n / 4 / 256, 256>>>(x, (bf16*)xhi, (bf16*)xlo, n);
    }
    {
        int n = STATE * DMODEL;
        k_cvt<<<n / 4 / 256, 256>>>(Wa, (bf16*)wabhi, (bf16*)wablo, n);
        k_cvt<<<n / 4 / 256, 256>>>(Bw, (bf16*)wabhi + n, (bf16*)wablo + n, n);
        k_cvt<<<n / 4 / 256, 256>>>(Cw, (bf16*)chi, (bf16*)clo, n);
    }
    {
        int n = DMODEL * DMODEL;
        k_cvt<<<n / 4 / 256, 256>>>(Dw, (bf16*)dhi, (bf16*)dlo, n);
    }

    k_gemm1<<<dim3(4, MTOT / 128), 256, SMEM_SZ>>>(Wab);

    k_scan_agg<<<dim3(NCHUNK, BATCH), 256>>>();
    k_scan_carry<<<BATCH, 256>>>();
    k_scan_apply<<<dim3(NCHUNK, BATCH), 256>>>();

    k_gemm2<<<dim3(DMODEL / 128, MTOT / 128), 256, SMEM_SZ>>>(out);
}